// round 15
// baseline (speedup 1.0000x reference)
#include <cuda_runtime.h>
#include <cstdint>

#define NN 10000
#define EE 320000
#define INC 26
#define LMD 512
#define HIDC 256
#define OUTC 128
#define G4 2048
#define TSTEPS 10000

#define L0_CTAS 32
#define L1_CTAS 64
#define NCTAS (L0_CTAS + L1_CTAS)

__device__ float g_XG0[(size_t)NN * G4];
__device__ float g_H0[(size_t)NN * LMD];
__device__ float g_H1[(size_t)NN * LMD];
__device__ float g_TMPZ[(size_t)NN * LMD];
__device__ float g_Z[(size_t)NN * LMD];
__device__ float g_T1[(size_t)NN * HIDC];
__device__ float g_O1[(size_t)NN * HIDC];
__device__ float g_T2[(size_t)NN * HIDC];
__device__ float g_O2[(size_t)NN * HIDC];
__device__ float g_T3[(size_t)NN * OUTC];
__device__ float g_NORM[EE];
__device__ float g_DEG[NN];
__device__ float g_DINV[NN];
__device__ int g_idx64;

__device__ __forceinline__ float sigf(float x) { return 1.0f / (1.0f + __expf(-x)); }
__device__ __forceinline__ float tanhf_(float x) { return 1.0f - 2.0f / (__expf(2.0f * x) + 1.0f); }
__device__ __forceinline__ int edge_at(const void* ei, long long pos) {
    return g_idx64 ? (int)((const long long*)ei)[pos] : ((const int*)ei)[pos];
}
__device__ __forceinline__ float4 ldvol4(const float4* p) {
    float4 v;
    asm volatile("ld.volatile.global.v4.f32 {%0,%1,%2,%3}, [%4];"
                 : "=f"(v.x), "=f"(v.y), "=f"(v.z), "=f"(v.w) : "l"(p));
    return v;
}
__device__ __forceinline__ int bad4(float4 v) {
    return (v.x != v.x) || (v.y != v.y) || (v.z != v.z) || (v.w != v.w);
}
// pipelined data-spin: two probes in flight, test the older -> ~half detection period
__device__ __forceinline__ void stage_spin(float* dst, const float4* src) {
    float4 a = ldvol4(src);
    float4 b = ldvol4(src);
    while (bad4(a)) {
        a = b;
        b = ldvol4(src);
    }
    *(float4*)dst = a;
}
#define BAR_SYNC(id, cnt) asm volatile("bar.sync %0, %1;" :: "r"(id), "r"(cnt) : "memory")

// fill both h buffers with quiet-NaN sentinels (16B granularity)
__global__ void k_fillnan2(float* p0, float* p1, int n4) {
    int i = blockIdx.x * 256 + threadIdx.x;
    float q = __uint_as_float(0x7FC00000u);
    float4 qv = make_float4(q, q, q, q);
    if (i < n4) ((float4*)p0)[i] = qv;
    else if (i < 2 * n4) ((float4*)p1)[i - n4] = qv;
}

// detect int64 vs int32 edge_index
__global__ void k_detect(const unsigned int* __restrict__ w) {
    __shared__ unsigned int s;
    if (threadIdx.x == 0) s = 0u;
    __syncthreads();
    unsigned int v = w[2 * threadIdx.x + 1] | w[2 * (threadIdx.x + 256) + 1] |
                     w[2 * (threadIdx.x + 512) + 1] | w[2 * (threadIdx.x + 768) + 1];
    if (v) atomicOr(&s, 1u);
    __syncthreads();
    if (threadIdx.x == 0) g_idx64 = (s == 0u) ? 1 : 0;
}

__global__ void k_deg_init() {
    int i = blockIdx.x * 256 + threadIdx.x;
    if (i < NN) g_DEG[i] = 1.0f;
}
__global__ void k_deg_edges(const void* __restrict__ ei, const float* __restrict__ ew) {
    int e = blockIdx.x * 256 + threadIdx.x;
    if (e >= EE) return;
    int dst = edge_at(ei, EE + e);
    if ((unsigned)dst < NN) atomicAdd(&g_DEG[dst], ew[e]);
}
__global__ void k_dinv() {
    int i = blockIdx.x * 256 + threadIdx.x;
    if (i < NN) g_DINV[i] = rsqrtf(g_DEG[i]);
}
__global__ void k_norm(const void* __restrict__ ei, const float* __restrict__ ew) {
    int e = blockIdx.x * 256 + threadIdx.x;
    if (e >= EE) return;
    int s = edge_at(ei, e), d = edge_at(ei, EE + e);
    float v = 0.f;
    if ((unsigned)s < NN && (unsigned)d < NN) v = g_DINV[s] * ew[e] * g_DINV[d];
    g_NORM[e] = v;
}

// XG0[t,r] = x[t,:] . Wih0[r,:] + bih0[r] + bhh0[r]
__global__ void k_xg0(const float* __restrict__ x, const float* __restrict__ Wih0,
                      const float* __restrict__ bih0, const float* __restrict__ bhh0) {
    __shared__ float xs[16][INC];
    int t0 = blockIdx.x * 16;
    for (int i = threadIdx.x; i < 16 * INC; i += 256) xs[i / INC][i % INC] = x[(size_t)(t0 + i / INC) * INC + i % INC];
    __syncthreads();
    for (int r = threadIdx.x; r < G4; r += 256) {
        float w[INC];
#pragma unroll
        for (int k = 0; k < INC; k++) w[k] = Wih0[r * INC + k];
        float bb = bih0[r] + bhh0[r];
#pragma unroll
        for (int tt = 0; tt < 16; tt++) {
            float a = bb;
#pragma unroll
            for (int k = 0; k < INC; k++) a = fmaf(xs[tt][k], w[k], a);
            g_XG0[(size_t)(t0 + tt) * G4 + r] = a;
        }
    }
}

// TMPZ[t,n] = x[t,:] @ aaW[:,n]
__global__ void k_tmpz(const float* __restrict__ x, const float* __restrict__ aaW) {
    __shared__ float xs[16][INC];
    int t0 = blockIdx.x * 16;
    for (int i = threadIdx.x; i < 16 * INC; i += 256) xs[i / INC][i % INC] = x[(size_t)(t0 + i / INC) * INC + i % INC];
    __syncthreads();
    int n = threadIdx.x;
    float a0[16], a1[16];
#pragma unroll
    for (int tt = 0; tt < 16; tt++) { a0[tt] = 0.f; a1[tt] = 0.f; }
#pragma unroll
    for (int k = 0; k < INC; k++) {
        float w0 = aaW[k * LMD + n], w1 = aaW[k * LMD + n + 256];
#pragma unroll
        for (int tt = 0; tt < 16; tt++) {
            a0[tt] = fmaf(xs[tt][k], w0, a0[tt]);
            a1[tt] = fmaf(xs[tt][k], w1, a1[tt]);
        }
    }
#pragma unroll
    for (int tt = 0; tt < 16; tt++) {
        g_TMPZ[(size_t)(t0 + tt) * LMD + n] = a0[tt];
        g_TMPZ[(size_t)(t0 + tt) * LMD + n + 256] = a1[tt];
    }
}

// ---------------- pipelined dual-layer LSTM scan (512 threads/CTA) ----------
// L0 (CTAs 0..31): as R10 — stage+bar+matvec+bar+gates(warp0).
// L1 (CTAs 32..95): SPLIT-PHASE.
//   Feeder (warps 0-7): stage h0[t] -> bar1 -> Wih1·h0[t]+bias per unit ->
//     deposit float4 gate partials into 2-deep smem ring (NaN handshake).
//   Consumer (warps 8-15): stage h1[t-1] -> bar2 -> Whh1·h1 per unit ->
//     lane0: grab ring entry, gates, publish. No block barrier in loop.
__global__ void __launch_bounds__(512, 1) k_scan(
        const float* __restrict__ Whh0, const float* __restrict__ Wih1,
        const float* __restrict__ Whh1, const float* __restrict__ bih1,
        const float* __restrict__ bhh1) {
    const int b = blockIdx.x;
    const int tid = threadIdx.x;
    const int lane = tid & 31;
    const int wid = tid >> 5;

    __shared__ __align__(16) float hA[LMD];       // L0 staging
    __shared__ __align__(16) float gsum[64];      // L0 reduce
    __shared__ __align__(16) float hF[2 * LMD];   // L1 feeder h0 staging (parity)
    __shared__ __align__(16) float hC[2 * LMD];   // L1 consumer h1 staging (parity)
    __shared__ __align__(16) float4 xgRing[2][8]; // L1 gate-partial ring (NaN=empty)

    if (b < L0_CTAS) {
        // ================= layer 0 (R10 structure) =================
        const int u0 = b * 16;
        const int row = tid >> 3, sub = tid & 7;   // 64 rows x 8 threads
        float4 wv[16];
        {
            int grow = (row >> 4) * LMD + u0 + (row & 15);
            const float* wp = Whh0 + (size_t)grow * LMD;
#pragma unroll
            for (int j = 0; j < 16; j++) wv[j] = *(const float4*)(wp + j * 32 + sub * 4);
        }
        float cst = 0.f;
        for (int t = 0; t < TSTEPS; t++) {
            float xI = 0.f, xF = 0.f, xG = 0.f, xO = 0.f;
            if (tid < 16) {
                const float* xb = g_XG0 + (size_t)t * G4 + u0 + tid;
                xI = xb[0]; xF = xb[LMD]; xG = xb[2 * LMD]; xO = xb[3 * LMD];
            }
            if (tid < 128) {
                if (t > 0) stage_spin(&hA[tid * 4], (const float4*)(g_H0 + (size_t)(t - 1) * LMD) + tid);
                else       *(float4*)&hA[tid * 4] = make_float4(0.f, 0.f, 0.f, 0.f);
            }
            __syncthreads();                          // (B)
            float acc = 0.f;
#pragma unroll
            for (int j = 0; j < 16; j++) {
                float4 h = ((const float4*)hA)[j * 8 + sub];
                float4 w = wv[j];
                acc = fmaf(w.x, h.x, acc); acc = fmaf(w.y, h.y, acc);
                acc = fmaf(w.z, h.z, acc); acc = fmaf(w.w, h.w, acc);
            }
            acc += __shfl_down_sync(0xffffffffu, acc, 4, 8);
            acc += __shfl_down_sync(0xffffffffu, acc, 2, 8);
            acc += __shfl_down_sync(0xffffffffu, acc, 1, 8);
            if (sub == 0) gsum[row] = acc;
            __syncthreads();                          // (C)
            if (wid == 0 && lane < 16) {
                float gi = gsum[lane] + xI;
                float gf = gsum[16 + lane] + xF;
                float gg = gsum[32 + lane] + xG;
                float go = gsum[48 + lane] + xO;
                float iv = sigf(gi), fv = sigf(gf), ov = sigf(go), gv = tanhf_(gg);
                cst = fmaf(fv, cst, iv * gv);
                float hv = ov * tanhf_(cst);
                __stcg(g_H0 + (size_t)t * LMD + u0 + lane, hv);
            }
        }
    } else {
        // ================= layer 1 (split-phase) =================
        const int cb = b - L0_CTAS;
        const int u0 = cb * 8;
        const int q = lane >> 3, s = lane & 7;     // gate, column-slice within warp
        const float qn = __uint_as_float(0x7FC00000u);

        // init smem: hC[parity 0] zeros (h1[-1]=0), ring empty
        for (int i = tid; i < LMD; i += 512) hC[i] = 0.f;
        if (tid < 16) ((float4*)xgRing)[tid] = make_float4(qn, qn, qn, qn);
        __syncthreads();

        if (wid < 8) {
            // ---- feeder: Wih1 · h0[t] + bias ----
            const int u = wid;
            float4 wv[16];
            {
                const float* wp = Wih1 + (size_t)(q * LMD + u0 + u) * LMD;
#pragma unroll
                for (int j = 0; j < 16; j++) wv[j] = *(const float4*)(wp + (j * 8 + s) * 4);
            }
            float bq = 0.f;
            if (s == 0) bq = bih1[q * LMD + u0 + u] + bhh1[q * LMD + u0 + u];

            for (int t = 0; t < TSTEPS; t++) {
                int slot = t & 1;
                if (lane == 0) {
                    volatile float* vr = (volatile float*)&xgRing[slot][u];
                    while (vr[0] == vr[0]) {}          // wait slot empty (NaN)
                }
                if (tid < 128)
                    stage_spin(&hF[slot * LMD + tid * 4],
                               (const float4*)(g_H0 + (size_t)t * LMD) + tid);
                BAR_SYNC(1, 256);
                const float4* h4 = (const float4*)(hF + slot * LMD);
                float acc = bq;
#pragma unroll
                for (int j = 0; j < 16; j++) {
                    float4 h = h4[j * 8 + s];
                    float4 w = wv[j];
                    acc = fmaf(w.x, h.x, acc); acc = fmaf(w.y, h.y, acc);
                    acc = fmaf(w.z, h.z, acc); acc = fmaf(w.w, h.w, acc);
                }
                acc += __shfl_down_sync(0xffffffffu, acc, 4, 8);
                acc += __shfl_down_sync(0xffffffffu, acc, 2, 8);
                acc += __shfl_down_sync(0xffffffffu, acc, 1, 8);
                float g0 = __shfl_sync(0xffffffffu, acc, 0);
                float g1 = __shfl_sync(0xffffffffu, acc, 8);
                float g2 = __shfl_sync(0xffffffffu, acc, 16);
                float g3 = __shfl_sync(0xffffffffu, acc, 24);
                if (lane == 0) xgRing[slot][u] = make_float4(g0, g1, g2, g3);
            }
        } else {
            // ---- consumer: Whh1 · h1[t-1] -> gates -> publish ----
            const int u = wid - 8;
            float4 wv[16];
            {
                const float* wp = Whh1 + (size_t)(q * LMD + u0 + u) * LMD;
#pragma unroll
                for (int j = 0; j < 16; j++) wv[j] = *(const float4*)(wp + (j * 8 + s) * 4);
            }
            float cst = 0.f;
            const int widx = tid - 256;               // 0..255; stagers widx<128

            for (int t = 0; t < TSTEPS; t++) {
                int slot = t & 1;
                if (t > 0 && widx < 128)
                    stage_spin(&hC[slot * LMD + widx * 4],
                               (const float4*)(g_H1 + (size_t)(t - 1) * LMD) + widx);
                BAR_SYNC(2, 256);
                const float4* h4 = (const float4*)(hC + slot * LMD);
                float acc = 0.f;
#pragma unroll
                for (int j = 0; j < 16; j++) {
                    float4 h = h4[j * 8 + s];
                    float4 w = wv[j];
                    acc = fmaf(w.x, h.x, acc); acc = fmaf(w.y, h.y, acc);
                    acc = fmaf(w.z, h.z, acc); acc = fmaf(w.w, h.w, acc);
                }
                acc += __shfl_down_sync(0xffffffffu, acc, 4, 8);
                acc += __shfl_down_sync(0xffffffffu, acc, 2, 8);
                acc += __shfl_down_sync(0xffffffffu, acc, 1, 8);
                float g0 = __shfl_sync(0xffffffffu, acc, 0);
                float g1 = __shfl_sync(0xffffffffu, acc, 8);
                float g2 = __shfl_sync(0xffffffffu, acc, 16);
                float g3 = __shfl_sync(0xffffffffu, acc, 24);
                if (lane == 0) {
                    volatile float* vr = (volatile float*)&xgRing[slot][u];
                    float x0, x1, x2, x3;
                    do {
                        x0 = vr[0]; x1 = vr[1]; x2 = vr[2]; x3 = vr[3];
                    } while (x0 != x0 || x1 != x1 || x2 != x2 || x3 != x3);
                    xgRing[slot][u] = make_float4(qn, qn, qn, qn);   // mark consumed
                    float gi = g0 + x0, gf = g1 + x1, gg = g2 + x2, go = g3 + x3;
                    float iv = sigf(gi), fv = sigf(gf), ov = sigf(go), gv = tanhf_(gg);
                    cst = fmaf(fv, cst, iv * gv);
                    float hv = ov * tanhf_(cst);
                    __stcg(g_H1 + (size_t)t * LMD + u0 + u, hv);
                }
            }
        }
    }
}

// out = A[MxK]@B[KxN]  (flags: 1 add Cin, 2 add bias, 4 relu). N%64==0, K%16==0.
__global__ void __launch_bounds__(256) k_gemm(
        const float* __restrict__ A, const float* __restrict__ B,
        const float* __restrict__ Cin, const float* __restrict__ bias,
        float* __restrict__ out, int M, int N, int K, int flags) {
    __shared__ float As[16][65];
    __shared__ float Bs[16][64];
    int tid = threadIdx.x, tx = tid & 15, ty = tid >> 4;
    int m0 = blockIdx.y * 64, n0 = blockIdx.x * 64;
    float acc[4][4];
#pragma unroll
    for (int i = 0; i < 4; i++)
#pragma unroll
        for (int j = 0; j < 4; j++) acc[i][j] = 0.f;
    int ka = tid & 15, ma = tid >> 4;
    int nb = tid & 63, kb = tid >> 6;
    for (int k0 = 0; k0 < K; k0 += 16) {
#pragma unroll
        for (int p = 0; p < 4; p++) {
            int m = ma + p * 16, gm = m0 + m;
            As[ka][m] = (gm < M) ? A[(size_t)gm * K + k0 + ka] : 0.f;
        }
#pragma unroll
        for (int p = 0; p < 4; p++) {
            int k = kb + p * 4;
            Bs[k][nb] = B[(size_t)(k0 + k) * N + n0 + nb];
        }
        __syncthreads();
#pragma unroll
        for (int kx = 0; kx < 16; kx++) {
            float a0 = As[kx][ty * 4], a1 = As[kx][ty * 4 + 1], a2 = As[kx][ty * 4 + 2], a3 = As[kx][ty * 4 + 3];
            float b0 = Bs[kx][tx * 4], b1 = Bs[kx][tx * 4 + 1], b2 = Bs[kx][tx * 4 + 2], b3 = Bs[kx][tx * 4 + 3];
            acc[0][0] = fmaf(a0, b0, acc[0][0]); acc[0][1] = fmaf(a0, b1, acc[0][1]);
            acc[0][2] = fmaf(a0, b2, acc[0][2]); acc[0][3] = fmaf(a0, b3, acc[0][3]);
            acc[1][0] = fmaf(a1, b0, acc[1][0]); acc[1][1] = fmaf(a1, b1, acc[1][1]);
            acc[1][2] = fmaf(a1, b2, acc[1][2]); acc[1][3] = fmaf(a1, b3, acc[1][3]);
            acc[2][0] = fmaf(a2, b0, acc[2][0]); acc[2][1] = fmaf(a2, b1, acc[2][1]);
            acc[2][2] = fmaf(a2, b2, acc[2][2]); acc[2][3] = fmaf(a2, b3, acc[2][3]);
            acc[3][0] = fmaf(a3, b0, acc[3][0]); acc[3][1] = fmaf(a3, b1, acc[3][1]);
            acc[3][2] = fmaf(a3, b2, acc[3][2]); acc[3][3] = fmaf(a3, b3, acc[3][3]);
        }
        __syncthreads();
    }
#pragma unroll
    for (int i = 0; i < 4; i++) {
        int gm = m0 + ty * 4 + i;
        if (gm >= M) continue;
#pragma unroll
        for (int j = 0; j < 4; j++) {
            int gn = n0 + tx * 4 + j;
            float v = acc[i][j];
            if (flags & 1) v += Cin[(size_t)gm * N + gn];
            if (flags & 2) v += bias[gn];
            if (flags & 4) v = fmaxf(v, 0.f);
            out[(size_t)gm * N + gn] = v;
        }
    }
}

// O[i,c] = T[i,c]*dinv[i]^2 + bias[c]
__global__ void k_scinit(const float* __restrict__ T, const float* __restrict__ bias,
                         float* __restrict__ O, int shiftC) {
    int idx = blockIdx.x * 256 + threadIdx.x;
    int C = 1 << shiftC;
    if (idx >= NN * C) return;
    int i = idx >> shiftC;
    float dv = g_DINV[i];
    O[idx] = fmaf(T[idx], dv * dv, bias[idx & (C - 1)]);
}

// per edge: O[dst,:] += T[src,:] * norm[e]
__global__ void k_scatter(const float* __restrict__ T, const void* __restrict__ ei,
                          float* __restrict__ O, int C, int s) {
    int e = blockIdx.x * (256 >> s) + (threadIdx.x >> s);
    if (e >= EE) return;
    int qq = threadIdx.x & ((1 << s) - 1);
    int src = edge_at(ei, e), dst = edge_at(ei, EE + e);
    if ((unsigned)src >= NN || (unsigned)dst >= NN) return;
    float nv = g_NORM[e];
    const float4 v = *(const float4*)(T + (size_t)src * C + qq * 4);
    float* o = O + (size_t)dst * C + qq * 4;
    atomicAdd(o + 0, v.x * nv);
    atomicAdd(o + 1, v.y * nv);
    atomicAdd(o + 2, v.z * nv);
    atomicAdd(o + 3, v.w * nv);
}

__global__ void k_relu(float* __restrict__ O, int total) {
    int idx = blockIdx.x * 256 + threadIdx.x;
    if (idx < total) O[idx] = fmaxf(O[idx], 0.f);
}

extern "C" void kernel_launch(void* const* d_in, const int* in_sizes, int n_in,
                              void* d_out, int out_size) {
    const float* x    = (const float*)d_in[0];
    const void*  ei   = d_in[1];
    const float* ew   = (const float*)d_in[2];
    const float* aaW  = (const float*)d_in[3];
    const float* lmW  = (const float*)d_in[4];
    const float* lmb  = (const float*)d_in[5];
    const float* Wih0 = (const float*)d_in[6];
    const float* Whh0 = (const float*)d_in[7];
    const float* bih0 = (const float*)d_in[8];
    const float* bhh0 = (const float*)d_in[9];
    const float* Wih1 = (const float*)d_in[10];
    const float* Whh1 = (const float*)d_in[11];
    const float* bih1 = (const float*)d_in[12];
    const float* bhh1 = (const float*)d_in[13];
    const float* W1   = (const float*)d_in[14];
    const float* b1   = (const float*)d_in[15];
    const float* W2   = (const float*)d_in[16];
    const float* b2   = (const float*)d_in[17];
    const float* W3   = (const float*)d_in[18];
    const float* b3   = (const float*)d_in[19];
    float* out = (float*)d_out;

    void* p;
    float *pH0, *pH1, *pTMPZ, *pZ, *pT1, *pO1, *pT2, *pO2, *pT3;
    cudaGetSymbolAddress(&p, g_H0);   pH0   = (float*)p;
    cudaGetSymbolAddress(&p, g_H1);   pH1   = (float*)p;
    cudaGetSymbolAddress(&p, g_TMPZ); pTMPZ = (float*)p;
    cudaGetSymbolAddress(&p, g_Z);    pZ    = (float*)p;
    cudaGetSymbolAddress(&p, g_T1);   pT1   = (float*)p;
    cudaGetSymbolAddress(&p, g_O1);   pO1   = (float*)p;
    cudaGetSymbolAddress(&p, g_T2);   pT2   = (float*)p;
    cudaGetSymbolAddress(&p, g_O2);   pO2   = (float*)p;
    cudaGetSymbolAddress(&p, g_T3);   pT3   = (float*)p;

    const int H4 = NN * LMD / 4;

    k_detect<<<1, 256>>>((const unsigned int*)ei);
    k_xg0<<<NN / 16, 256>>>(x, Wih0, bih0, bhh0);
    k_fillnan2<<<(2 * H4 + 255) / 256, 256>>>(pH0, pH1, H4);
    k_scan<<<NCTAS, 512>>>(Whh0, Wih1, Whh1, bih1, bhh1);
    k_tmpz<<<NN / 16, 256>>>(x, aaW);
    k_deg_init<<<(NN + 255) / 256, 256>>>();

    k_deg_edges<<<(EE + 255) / 256, 256>>>(ei, ew);
    k_dinv<<<(NN + 255) / 256, 256>>>();
    k_norm<<<(EE + 255) / 256, 256>>>(ei, ew);

    // Z = relu(TMPZ + H1 @ lmW + lmb)
    k_gemm<<<dim3(LMD / 64, (NN + 63) / 64), 256>>>(pH1, lmW, pTMPZ, lmb, pZ, NN, LMD, LMD, 1 | 2 | 4);

    k_gemm<<<dim3(HIDC / 64, (NN + 63) / 64), 256>>>(pZ, W1, nullptr, nullptr, pT1, NN, HIDC, LMD, 0);
    k_scinit<<<(NN * HIDC + 255) / 256, 256>>>(pT1, b1, pO1, 8);
    k_scatter<<<EE / 4, 256>>>(pT1, ei, pO1, HIDC, 6);
    k_relu<<<(NN * HIDC + 255) / 256, 256>>>(pO1, NN * HIDC);

    k_gemm<<<dim3(HIDC / 64, (NN + 63) / 64), 256>>>(pO1, W2, nullptr, nullptr, pT2, NN, HIDC, HIDC, 0);
    k_scinit<<<(NN * HIDC + 255) / 256, 256>>>(pT2, b2, pO2, 8);
    k_scatter<<<EE / 4, 256>>>(pT2, ei, pO2, HIDC, 6);
    k_relu<<<(NN * HIDC + 255) / 256, 256>>>(pO2, NN * HIDC);

    k_gemm<<<dim3(OUTC / 64, (NN + 63) / 64), 256>>>(pO2, W3, nullptr, nullptr, pT3, NN, OUTC, HIDC, 0);
    k_scinit<<<(NN * OUTC + 255) / 256, 256>>>(pT3, b3, out, 7);
    k_scatter<<<EE / 8, 256>>>(pT3, ei, out, OUTC, 5);
}

// round 16
// speedup vs baseline: 1.8710x; 1.8710x over previous
#include <cuda_runtime.h>
#include <cstdint>

#define NN 10000
#define EE 320000
#define INC 26
#define LMD 512
#define HIDC 256
#define OUTC 128
#define G4 2048
#define TSTEPS 10000

#define L0_CTAS 32
#define L1_CTAS 64
#define NCTAS (L0_CTAS + L1_CTAS)

__device__ float g_XG0[(size_t)NN * G4];
__device__ float g_H0[(size_t)NN * LMD];
__device__ float g_H1[(size_t)NN * LMD];
__device__ float g_TMPZ[(size_t)NN * LMD];
__device__ float g_Z[(size_t)NN * LMD];
__device__ float g_T1[(size_t)NN * HIDC];
__device__ float g_O1[(size_t)NN * HIDC];
__device__ float g_T2[(size_t)NN * HIDC];
__device__ float g_O2[(size_t)NN * HIDC];
__device__ float g_T3[(size_t)NN * OUTC];
__device__ float g_NORM[EE];
__device__ float g_DEG[NN];
__device__ float g_DINV[NN];
__device__ int g_idx64;

__device__ __forceinline__ float sigf(float x) { return 1.0f / (1.0f + __expf(-x)); }
__device__ __forceinline__ float tanhf_(float x) { return 1.0f - 2.0f / (__expf(2.0f * x) + 1.0f); }
__device__ __forceinline__ int edge_at(const void* ei, long long pos) {
    return g_idx64 ? (int)((const long long*)ei)[pos] : ((const int*)ei)[pos];
}
// volatile 16B load (bypasses L1, hits L2 every probe)
__device__ __forceinline__ float4 ldvol4(const float4* p) {
    float4 v;
    asm volatile("ld.volatile.global.v4.f32 {%0,%1,%2,%3}, [%4];"
                 : "=f"(v.x), "=f"(v.y), "=f"(v.z), "=f"(v.w) : "l"(p));
    return v;
}
// spin until all 4 components are non-NaN (values are self-validating), then stage
__device__ __forceinline__ void stage_spin(float* dst, const float4* src) {
    float4 v = ldvol4(src);
    while (v.x != v.x || v.y != v.y || v.z != v.z || v.w != v.w) v = ldvol4(src);
    *(float4*)dst = v;
}
// packed f32x2 FMA: acc += a * b (elementwise on 2 packed floats)
__device__ __forceinline__ void ffma2(unsigned long long& acc, unsigned long long a, unsigned long long b) {
    asm("fma.rn.f32x2 %0, %1, %2, %0;" : "+l"(acc) : "l"(a), "l"(b));
}
__device__ __forceinline__ float unpack_sum(unsigned long long v) {
    float lo = __uint_as_float((unsigned)(v & 0xffffffffull));
    float hi = __uint_as_float((unsigned)(v >> 32));
    return lo + hi;
}

// fill both h buffers with quiet-NaN sentinels (16B granularity)
__global__ void k_fillnan2(float* p0, float* p1, int n4) {
    int i = blockIdx.x * 256 + threadIdx.x;
    float q = __uint_as_float(0x7FC00000u);
    float4 qv = make_float4(q, q, q, q);
    if (i < n4) ((float4*)p0)[i] = qv;
    else if (i < 2 * n4) ((float4*)p1)[i - n4] = qv;
}

// detect int64 vs int32 edge_index
__global__ void k_detect(const unsigned int* __restrict__ w) {
    __shared__ unsigned int s;
    if (threadIdx.x == 0) s = 0u;
    __syncthreads();
    unsigned int v = w[2 * threadIdx.x + 1] | w[2 * (threadIdx.x + 256) + 1] |
                     w[2 * (threadIdx.x + 512) + 1] | w[2 * (threadIdx.x + 768) + 1];
    if (v) atomicOr(&s, 1u);
    __syncthreads();
    if (threadIdx.x == 0) g_idx64 = (s == 0u) ? 1 : 0;
}

__global__ void k_deg_init() {
    int i = blockIdx.x * 256 + threadIdx.x;
    if (i < NN) g_DEG[i] = 1.0f;
}
__global__ void k_deg_edges(const void* __restrict__ ei, const float* __restrict__ ew) {
    int e = blockIdx.x * 256 + threadIdx.x;
    if (e >= EE) return;
    int dst = edge_at(ei, EE + e);
    if ((unsigned)dst < NN) atomicAdd(&g_DEG[dst], ew[e]);
}
__global__ void k_dinv() {
    int i = blockIdx.x * 256 + threadIdx.x;
    if (i < NN) g_DINV[i] = rsqrtf(g_DEG[i]);
}
__global__ void k_norm(const void* __restrict__ ei, const float* __restrict__ ew) {
    int e = blockIdx.x * 256 + threadIdx.x;
    if (e >= EE) return;
    int s = edge_at(ei, e), d = edge_at(ei, EE + e);
    float v = 0.f;
    if ((unsigned)s < NN && (unsigned)d < NN) v = g_DINV[s] * ew[e] * g_DINV[d];
    g_NORM[e] = v;
}

// XG0[t,r] = x[t,:] . Wih0[r,:] + bih0[r] + bhh0[r]
__global__ void k_xg0(const float* __restrict__ x, const float* __restrict__ Wih0,
                      const float* __restrict__ bih0, const float* __restrict__ bhh0) {
    __shared__ float xs[16][INC];
    int t0 = blockIdx.x * 16;
    for (int i = threadIdx.x; i < 16 * INC; i += 256) xs[i / INC][i % INC] = x[(size_t)(t0 + i / INC) * INC + i % INC];
    __syncthreads();
    for (int r = threadIdx.x; r < G4; r += 256) {
        float w[INC];
#pragma unroll
        for (int k = 0; k < INC; k++) w[k] = Wih0[r * INC + k];
        float bb = bih0[r] + bhh0[r];
#pragma unroll
        for (int tt = 0; tt < 16; tt++) {
            float a = bb;
#pragma unroll
            for (int k = 0; k < INC; k++) a = fmaf(xs[tt][k], w[k], a);
            g_XG0[(size_t)(t0 + tt) * G4 + r] = a;
        }
    }
}

// TMPZ[t,n] = x[t,:] @ aaW[:,n]
__global__ void k_tmpz(const float* __restrict__ x, const float* __restrict__ aaW) {
    __shared__ float xs[16][INC];
    int t0 = blockIdx.x * 16;
    for (int i = threadIdx.x; i < 16 * INC; i += 256) xs[i / INC][i % INC] = x[(size_t)(t0 + i / INC) * INC + i % INC];
    __syncthreads();
    int n = threadIdx.x;
    float a0[16], a1[16];
#pragma unroll
    for (int tt = 0; tt < 16; tt++) { a0[tt] = 0.f; a1[tt] = 0.f; }
#pragma unroll
    for (int k = 0; k < INC; k++) {
        float w0 = aaW[k * LMD + n], w1 = aaW[k * LMD + n + 256];
#pragma unroll
        for (int tt = 0; tt < 16; tt++) {
            a0[tt] = fmaf(xs[tt][k], w0, a0[tt]);
            a1[tt] = fmaf(xs[tt][k], w1, a1[tt]);
        }
    }
#pragma unroll
    for (int tt = 0; tt < 16; tt++) {
        g_TMPZ[(size_t)(t0 + tt) * LMD + n] = a0[tt];
        g_TMPZ[(size_t)(t0 + tt) * LMD + n + 256] = a1[tt];
    }
}

// ---------------- pipelined dual-layer LSTM scan (512 threads/CTA) ----------
// Structure identical to R10; matvec uses packed fma.rn.f32x2
// (32 FFMA2/thread instead of 64 FFMA -> half the FMA issue cycles/SMSP).
// CTAs 0..31  : layer 0, 16 units each (64 gate rows x 8 threads/row)
// CTAs 32..95 : layer 1, 8 units each (32 gate rows x 16 threads/row)
__global__ void __launch_bounds__(512, 1) k_scan(
        const float* __restrict__ Whh0, const float* __restrict__ Wih1,
        const float* __restrict__ Whh1, const float* __restrict__ bih1,
        const float* __restrict__ bhh1) {
    const int b = blockIdx.x;
    const int tid = threadIdx.x;
    const int lane = tid & 31;
    const int wid = tid >> 5;
    const bool isL1 = (b >= L0_CTAS);

    __shared__ __align__(16) float hA[LMD];
    __shared__ __align__(16) float hB[LMD];
    __shared__ __align__(16) float gsum[64];

    unsigned long long wu[32];   // 64 packed weight floats (same reg count as float4[16])
    int u0, row, sub;
    if (!isL1) {
        u0 = b * 16;
        row = tid >> 3; sub = tid & 7;              // 64 rows x 8 threads
        int grow = (row >> 4) * LMD + u0 + (row & 15);
        const float* wp = Whh0 + (size_t)grow * LMD;
#pragma unroll
        for (int j = 0; j < 16; j++) {
            ulonglong2 w = *(const ulonglong2*)(wp + j * 32 + sub * 4);
            wu[2 * j] = w.x; wu[2 * j + 1] = w.y;
        }
    } else {
        u0 = (b - L0_CTAS) * 8;
        row = tid >> 4; sub = tid & 15;             // 32 rows x 16 threads
        int grow = (row >> 3) * LMD + u0 + (row & 7);
        const float* wp1 = Wih1 + (size_t)grow * LMD;
        const float* wp2 = Whh1 + (size_t)grow * LMD;
#pragma unroll
        for (int j = 0; j < 8; j++) {
            ulonglong2 w1 = *(const ulonglong2*)(wp1 + j * 64 + sub * 4);
            ulonglong2 w2 = *(const ulonglong2*)(wp2 + j * 64 + sub * 4);
            wu[2 * j] = w1.x; wu[2 * j + 1] = w1.y;
            wu[16 + 2 * j] = w2.x; wu[16 + 2 * j + 1] = w2.y;
        }
    }
    float bI = 0.f, bF = 0.f, bG = 0.f, bO = 0.f;
    if (isL1 && tid < 8) {
        int u = u0 + tid;
        bI = bih1[u] + bhh1[u];
        bF = bih1[LMD + u] + bhh1[LMD + u];
        bG = bih1[2 * LMD + u] + bhh1[2 * LMD + u];
        bO = bih1[3 * LMD + u] + bhh1[3 * LMD + u];
    }
    float cst = 0.f;

    for (int t = 0; t < TSTEPS; t++) {
        float xI = bI, xF = bF, xG = bG, xO = bO;
        if (!isL1 && tid < 16) {
            const float* xb = g_XG0 + (size_t)t * G4 + u0 + tid;
            xI = xb[0]; xF = xb[LMD]; xG = xb[2 * LMD]; xO = xb[3 * LMD];
        }
        // stage h vectors into smem: data-spin (NaN sentinel), max probe rate
        if (!isL1) {
            if (tid < 128) {
                if (t > 0) stage_spin(&hA[tid * 4], (const float4*)(g_H0 + (size_t)(t - 1) * LMD) + tid);
                else       *(float4*)&hA[tid * 4] = make_float4(0.f, 0.f, 0.f, 0.f);
            }
        } else {
            if (tid < 128) {
                stage_spin(&hA[tid * 4], (const float4*)(g_H0 + (size_t)t * LMD) + tid);
            } else if (tid < 256) {
                int i = tid - 128;
                if (t > 0) stage_spin(&hB[i * 4], (const float4*)(g_H1 + (size_t)(t - 1) * LMD) + i);
                else       *(float4*)&hB[i * 4] = make_float4(0.f, 0.f, 0.f, 0.f);
            }
        }
        __syncthreads();                                  // (B) h staged
        // matvec slice: 32 packed FFMA2/thread
        unsigned long long ac0 = 0ull, ac1 = 0ull;
        if (!isL1) {
#pragma unroll
            for (int j = 0; j < 16; j++) {
                ulonglong2 h = *(const ulonglong2*)&hA[(j * 8 + sub) * 4];
                ffma2(ac0, wu[2 * j], h.x);
                ffma2(ac1, wu[2 * j + 1], h.y);
            }
        } else {
#pragma unroll
            for (int j = 0; j < 8; j++) {
                ulonglong2 h = *(const ulonglong2*)&hA[(j * 16 + sub) * 4];
                ulonglong2 g = *(const ulonglong2*)&hB[(j * 16 + sub) * 4];
                ffma2(ac0, wu[2 * j], h.x);
                ffma2(ac1, wu[2 * j + 1], h.y);
                ffma2(ac0, wu[16 + 2 * j], g.x);
                ffma2(ac1, wu[16 + 2 * j + 1], g.y);
            }
        }
        float acc = unpack_sum(ac0) + unpack_sum(ac1);
        if (!isL1) {
            acc += __shfl_down_sync(0xffffffffu, acc, 4, 8);
            acc += __shfl_down_sync(0xffffffffu, acc, 2, 8);
            acc += __shfl_down_sync(0xffffffffu, acc, 1, 8);
        } else {
            acc += __shfl_down_sync(0xffffffffu, acc, 8, 16);
            acc += __shfl_down_sync(0xffffffffu, acc, 4, 16);
            acc += __shfl_down_sync(0xffffffffu, acc, 2, 16);
            acc += __shfl_down_sync(0xffffffffu, acc, 1, 16);
        }
        if (sub == 0) gsum[row] = acc;
        __syncthreads();                                  // (C) gsum ready
        // gates + publish (warp 0); __stcg writes go straight to L2
        if (wid == 0) {
            const int NU = isL1 ? 8 : 16;
            if (lane < NU) {
                float gi = gsum[lane] + xI;
                float gf = gsum[NU + lane] + xF;
                float gg = gsum[2 * NU + lane] + xG;
                float go = gsum[3 * NU + lane] + xO;
                float iv = sigf(gi), fv = sigf(gf), ov = sigf(go), gv = tanhf_(gg);
                cst = fmaf(fv, cst, iv * gv);
                float hv = ov * tanhf_(cst);
                float* dp = (isL1 ? g_H1 : g_H0) + (size_t)t * LMD + u0;
                __stcg(dp + lane, hv);
            }
        }
        // gsum anti-hazard: other warps can't overwrite gsum until next (B),
        // which warp 0 must also reach after its gates/publish.
    }
}

// out = A[MxK]@B[KxN]  (flags: 1 add Cin, 2 add bias, 4 relu). N%64==0, K%16==0.
__global__ void __launch_bounds__(256) k_gemm(
        const float* __restrict__ A, const float* __restrict__ B,
        const float* __restrict__ Cin, const float* __restrict__ bias,
        float* __restrict__ out, int M, int N, int K, int flags) {
    __shared__ float As[16][65];
    __shared__ float Bs[16][64];
    int tid = threadIdx.x, tx = tid & 15, ty = tid >> 4;
    int m0 = blockIdx.y * 64, n0 = blockIdx.x * 64;
    float acc[4][4];
#pragma unroll
    for (int i = 0; i < 4; i++)
#pragma unroll
        for (int j = 0; j < 4; j++) acc[i][j] = 0.f;
    int ka = tid & 15, ma = tid >> 4;
    int nb = tid & 63, kb = tid >> 6;
    for (int k0 = 0; k0 < K; k0 += 16) {
#pragma unroll
        for (int p = 0; p < 4; p++) {
            int m = ma + p * 16, gm = m0 + m;
            As[ka][m] = (gm < M) ? A[(size_t)gm * K + k0 + ka] : 0.f;
        }
#pragma unroll
        for (int p = 0; p < 4; p++) {
            int k = kb + p * 4;
            Bs[k][nb] = B[(size_t)(k0 + k) * N + n0 + nb];
        }
        __syncthreads();
#pragma unroll
        for (int kx = 0; kx < 16; kx++) {
            float a0 = As[kx][ty * 4], a1 = As[kx][ty * 4 + 1], a2 = As[kx][ty * 4 + 2], a3 = As[kx][ty * 4 + 3];
            float b0 = Bs[kx][tx * 4], b1 = Bs[kx][tx * 4 + 1], b2 = Bs[kx][tx * 4 + 2], b3 = Bs[kx][tx * 4 + 3];
            acc[0][0] = fmaf(a0, b0, acc[0][0]); acc[0][1] = fmaf(a0, b1, acc[0][1]);
            acc[0][2] = fmaf(a0, b2, acc[0][2]); acc[0][3] = fmaf(a0, b3, acc[0][3]);
            acc[1][0] = fmaf(a1, b0, acc[1][0]); acc[1][1] = fmaf(a1, b1, acc[1][1]);
            acc[1][2] = fmaf(a1, b2, acc[1][2]); acc[1][3] = fmaf(a1, b3, acc[1][3]);
            acc[2][0] = fmaf(a2, b0, acc[2][0]); acc[2][1] = fmaf(a2, b1, acc[2][1]);
            acc[2][2] = fmaf(a2, b2, acc[2][2]); acc[2][3] = fmaf(a2, b3, acc[2][3]);
            acc[3][0] = fmaf(a3, b0, acc[3][0]); acc[3][1] = fmaf(a3, b1, acc[3][1]);
            acc[3][2] = fmaf(a3, b2, acc[3][2]); acc[3][3] = fmaf(a3, b3, acc[3][3]);
        }
        __syncthreads();
    }
#pragma unroll
    for (int i = 0; i < 4; i++) {
        int gm = m0 + ty * 4 + i;
        if (gm >= M) continue;
#pragma unroll
        for (int j = 0; j < 4; j++) {
            int gn = n0 + tx * 4 + j;
            float v = acc[i][j];
            if (flags & 1) v += Cin[(size_t)gm * N + gn];
            if (flags & 2) v += bias[gn];
            if (flags & 4) v = fmaxf(v, 0.f);
            out[(size_t)gm * N + gn] = v;
        }
    }
}

// O[i,c] = T[i,c]*dinv[i]^2 + bias[c]
__global__ void k_scinit(const float* __restrict__ T, const float* __restrict__ bias,
                         float* __restrict__ O, int shiftC) {
    int idx = blockIdx.x * 256 + threadIdx.x;
    int C = 1 << shiftC;
    if (idx >= NN * C) return;
    int i = idx >> shiftC;
    float dv = g_DINV[i];
    O[idx] = fmaf(T[idx], dv * dv, bias[idx & (C - 1)]);
}

// per edge: O[dst,:] += T[src,:] * norm[e]
__global__ void k_scatter(const float* __restrict__ T, const void* __restrict__ ei,
                          float* __restrict__ O, int C, int s) {
    int e = blockIdx.x * (256 >> s) + (threadIdx.x >> s);
    if (e >= EE) return;
    int qq = threadIdx.x & ((1 << s) - 1);
    int src = edge_at(ei, e), dst = edge_at(ei, EE + e);
    if ((unsigned)src >= NN || (unsigned)dst >= NN) return;
    float nv = g_NORM[e];
    const float4 v = *(const float4*)(T + (size_t)src * C + qq * 4);
    float* o = O + (size_t)dst * C + qq * 4;
    atomicAdd(o + 0, v.x * nv);
    atomicAdd(o + 1, v.y * nv);
    atomicAdd(o + 2, v.z * nv);
    atomicAdd(o + 3, v.w * nv);
}

__global__ void k_relu(float* __restrict__ O, int total) {
    int idx = blockIdx.x * 256 + threadIdx.x;
    if (idx < total) O[idx] = fmaxf(O[idx], 0.f);
}

extern "C" void kernel_launch(void* const* d_in, const int* in_sizes, int n_in,
                              void* d_out, int out_size) {
    const float* x    = (const float*)d_in[0];
    const void*  ei   = d_in[1];
    const float* ew   = (const float*)d_in[2];
    const float* aaW  = (const float*)d_in[3];
    const float* lmW  = (const float*)d_in[4];
    const float* lmb  = (const float*)d_in[5];
    const float* Wih0 = (const float*)d_in[6];
    const float* Whh0 = (const float*)d_in[7];
    const float* bih0 = (const float*)d_in[8];
    const float* bhh0 = (const float*)d_in[9];
    const float* Wih1 = (const float*)d_in[10];
    const float* Whh1 = (const float*)d_in[11];
    const float* bih1 = (const float*)d_in[12];
    const float* bhh1 = (const float*)d_in[13];
    const float* W1   = (const float*)d_in[14];
    const float* b1   = (const float*)d_in[15];
    const float* W2   = (const float*)d_in[16];
    const float* b2   = (const float*)d_in[17];
    const float* W3   = (const float*)d_in[18];
    const float* b3   = (const float*)d_in[19];
    float* out = (float*)d_out;

    void* p;
    float *pH0, *pH1, *pTMPZ, *pZ, *pT1, *pO1, *pT2, *pO2, *pT3;
    cudaGetSymbolAddress(&p, g_H0);   pH0   = (float*)p;
    cudaGetSymbolAddress(&p, g_H1);   pH1   = (float*)p;
    cudaGetSymbolAddress(&p, g_TMPZ); pTMPZ = (float*)p;
    cudaGetSymbolAddress(&p, g_Z);    pZ    = (float*)p;
    cudaGetSymbolAddress(&p, g_T1);   pT1   = (float*)p;
    cudaGetSymbolAddress(&p, g_O1);   pO1   = (float*)p;
    cudaGetSymbolAddress(&p, g_T2);   pT2   = (float*)p;
    cudaGetSymbolAddress(&p, g_O2);   pO2   = (float*)p;
    cudaGetSymbolAddress(&p, g_T3);   pT3   = (float*)p;

    const int H4 = NN * LMD / 4;   // float4 count per h buffer

    k_detect<<<1, 256>>>((const unsigned int*)ei);
    k_xg0<<<NN / 16, 256>>>(x, Wih0, bih0, bhh0);
    k_fillnan2<<<(2 * H4 + 255) / 256, 256>>>(pH0, pH1, H4);
    k_scan<<<NCTAS, 512>>>(Whh0, Wih1, Whh1, bih1, bhh1);
    k_tmpz<<<NN / 16, 256>>>(x, aaW);
    k_deg_init<<<(NN + 255) / 256, 256>>>();

    k_deg_edges<<<(EE + 255) / 256, 256>>>(ei, ew);
    k_dinv<<<(NN + 255) / 256, 256>>>();
    k_norm<<<(EE + 255) / 256, 256>>>(ei, ew);

    // Z = relu(TMPZ + H1 @ lmW + lmb)
    k_gemm<<<dim3(LMD / 64, (NN + 63) / 64), 256>>>(pH1, lmW, pTMPZ, lmb, pZ, NN, LMD, LMD, 1 | 2 | 4);

    k_gemm<<<dim3(HIDC / 64, (NN + 63) / 64), 256>>>(pZ, W1, nullptr, nullptr, pT1, NN, HIDC, LMD, 0);
    k_scinit<<<(NN * HIDC + 255) / 256, 256>>>(pT1, b1, pO1, 8);
    k_scatter<<<EE / 4, 256>>>(pT1, ei, pO1, HIDC, 6);
    k_relu<<<(NN * HIDC + 255) / 256, 256>>>(pO1, NN * HIDC);

    k_gemm<<<dim3(HIDC / 64, (NN + 63) / 64), 256>>>(pO1, W2, nullptr, nullptr, pT2, NN, HIDC, HIDC, 0);
    k_scinit<<<(NN * HIDC + 255) / 256, 256>>>(pT2, b2, pO2, 8);
    k_scatter<<<EE / 4, 256>>>(pT2, ei, pO2, HIDC, 6);
    k_relu<<<(NN * HIDC + 255) / 256, 256>>>(pO2, NN * HIDC);

    k_gemm<<<dim3(OUTC / 64, (NN + 63) / 64), 256>>>(pO2, W3, nullptr, nullptr, pT3, NN, OUTC, HIDC, 0);
    k_scinit<<<(NN * OUTC + 255) / 256, 256>>>(pT3, b3, out, 7);
    k_scatter<<<EE / 8, 256>>>(pT3, ei, out, OUTC, 5);
}